// round 1
// baseline (speedup 1.0000x reference)
#include <cuda_runtime.h>
#include <cstdint>

#define NNODES   100000
#define SSAMP    16
#define NODE_DIM 128
#define EDGE_DIM 64
#define EMB_DIM  128
#define KTOT     320   // 128 self + 128 neigh-agg + 64 edge-mean

// Scratch (allocation-free rule: __device__ globals)
__device__ float g_A [(size_t)NNODES * NODE_DIM];   // mean of gathered src node feats
__device__ float g_Eb[(size_t)NNODES * EDGE_DIM];   // mean of edge feats per node
__device__ float g_W [KTOT * EMB_DIM];              // folded weight [320,128]
__device__ float g_bias[EMB_DIM];                   // folded bias

// ---------------------------------------------------------------------------
// K0: fold weights.  Wall rows 0..255 = W_lin; rows 256..319 = W_edge @ W_lin[128:,:]
//     bias = b_lin + b_edge @ W_lin[128:,:]
// grid = 321 blocks x 128 threads
// ---------------------------------------------------------------------------
__global__ void prep_weights(const float* __restrict__ W_edge,
                             const float* __restrict__ b_edge,
                             const float* __restrict__ W_lin,
                             const float* __restrict__ b_lin) {
    int row = blockIdx.x;
    int j   = threadIdx.x;             // 0..127 output column
    if (row < 2 * NODE_DIM) {
        g_W[row * EMB_DIM + j] = W_lin[row * EMB_DIM + j];
    } else if (row < KTOT) {
        int e = row - 2 * NODE_DIM;    // 0..63
        float acc = 0.f;
        #pragma unroll 4
        for (int k = 0; k < NODE_DIM; k++)
            acc += W_edge[e * NODE_DIM + k] * W_lin[(NODE_DIM + k) * EMB_DIM + j];
        g_W[row * EMB_DIM + j] = acc;
    } else {
        float acc = b_lin[j];
        for (int k = 0; k < NODE_DIM; k++)
            acc += b_edge[k] * W_lin[(NODE_DIM + k) * EMB_DIM + j];
        g_bias[j] = acc;
    }
}

// ---------------------------------------------------------------------------
// K1: warp-per-node aggregation.
//   Ebar[n] = mean over 16 contiguous edge rows (64 floats each)
//   A[n]    = mean over 16 gathered node_feat rows (128 floats each, L2-resident)
// block = 256 threads (8 warps = 8 nodes), grid = NNODES/8
// ---------------------------------------------------------------------------
__global__ __launch_bounds__(256) void aggregate(const float* __restrict__ node_feat,
                                                 const float* __restrict__ edge_feat,
                                                 const int*   __restrict__ src_idx) {
    int node = (int)((blockIdx.x * blockDim.x + threadIdx.x) >> 5);
    if (node >= NNODES) return;
    int lane = threadIdx.x & 31;

    // ---- edge mean: lanes 0-15 take even rows, lanes 16-31 odd rows ----
    const float* ep = edge_feat + (size_t)node * (SSAMP * EDGE_DIM);
    int halfrow = lane >> 4;          // 0 or 1
    int cg      = lane & 15;          // column group (float4)
    float4 ea = make_float4(0.f, 0.f, 0.f, 0.f);
    #pragma unroll
    for (int r = 0; r < SSAMP; r += 2) {
        float4 v = *(const float4*)(ep + (size_t)(r + halfrow) * EDGE_DIM + cg * 4);
        ea.x += v.x; ea.y += v.y; ea.z += v.z; ea.w += v.w;
    }

    // ---- node gather mean ----
    int s = 0;
    if (lane < SSAMP) s = src_idx[(size_t)node * SSAMP + lane];
    float4 na = make_float4(0.f, 0.f, 0.f, 0.f);
    #pragma unroll
    for (int r = 0; r < SSAMP; r++) {
        int sr = __shfl_sync(0xffffffffu, s, r);
        float4 v = *(const float4*)(node_feat + (size_t)sr * NODE_DIM + lane * 4);
        na.x += v.x; na.y += v.y; na.z += v.z; na.w += v.w;
    }

    // combine edge halves across the warp
    ea.x += __shfl_xor_sync(0xffffffffu, ea.x, 16);
    ea.y += __shfl_xor_sync(0xffffffffu, ea.y, 16);
    ea.z += __shfl_xor_sync(0xffffffffu, ea.z, 16);
    ea.w += __shfl_xor_sync(0xffffffffu, ea.w, 16);

    const float inv = 1.0f / (float)SSAMP;
    if (lane < 16) {
        float4 o = make_float4(ea.x * inv, ea.y * inv, ea.z * inv, ea.w * inv);
        *(float4*)(g_Eb + (size_t)node * EDGE_DIM + cg * 4) = o;
    }
    float4 on = make_float4(na.x * inv, na.y * inv, na.z * inv, na.w * inv);
    *(float4*)(g_A + (size_t)node * NODE_DIM + lane * 4) = on;
}

// ---------------------------------------------------------------------------
// K2: out = relu( X @ Wall + bias ),  X = [node_feat | A | Ebar]  (virtual concat)
// Tile: 128 nodes x 128 cols, 256 threads, 8x8 micro-tile per thread, KC=32.
// ---------------------------------------------------------------------------
#define MT 128
#define KC 32

__global__ __launch_bounds__(256, 2) void fused_out_gemm(const float* __restrict__ node_feat,
                                                         float* __restrict__ out,
                                                         int n_nodes) {
    __shared__ float Xs[KC][MT + 4];       // transposed: Xs[k][m]
    __shared__ float Ws[KC][EMB_DIM + 4];  // Ws[k][n]

    const int m0 = blockIdx.x * MT;
    const int t  = threadIdx.x;
    const int tx = t & 15;                 // col group
    const int ty = t >> 4;                 // row group

    float c[8][8];
    #pragma unroll
    for (int i = 0; i < 8; i++)
        #pragma unroll
        for (int j = 0; j < 8; j++) c[i][j] = 0.f;

    #pragma unroll
    for (int ch = 0; ch < KTOT / KC; ch++) {   // 10 chunks of 32
        const float* src;
        int stride, koff;
        if (ch < 4)      { src = node_feat; stride = NODE_DIM; koff = ch * KC; }
        else if (ch < 8) { src = g_A;       stride = NODE_DIM; koff = (ch - 4) * KC; }
        else             { src = g_Eb;      stride = EDGE_DIM; koff = (ch - 8) * KC; }

        // load X tile (128 rows x 32 k), transposed into Xs
        #pragma unroll
        for (int p = 0; p < 4; p++) {
            int r  = p * 32 + (t >> 3);
            int kq = (t & 7) * 4;
            float4 v = make_float4(0.f, 0.f, 0.f, 0.f);
            int m = m0 + r;
            if (m < n_nodes)
                v = *(const float4*)(src + (size_t)m * stride + koff + kq);
            Xs[kq + 0][r] = v.x;
            Xs[kq + 1][r] = v.y;
            Xs[kq + 2][r] = v.z;
            Xs[kq + 3][r] = v.w;
        }
        // load W tile (32 rows x 128 cols)
        #pragma unroll
        for (int p = 0; p < 4; p++) {
            int kr = p * 8 + (t >> 5);
            int cq = (t & 31) * 4;
            *(float4*)&Ws[kr][cq] =
                *(const float4*)(g_W + (size_t)(ch * KC + kr) * EMB_DIM + cq);
        }
        __syncthreads();

        #pragma unroll
        for (int k = 0; k < KC; k++) {
            float a[8], b[8];
            *(float4*)&a[0] = *(const float4*)&Xs[k][ty * 8];
            *(float4*)&a[4] = *(const float4*)&Xs[k][ty * 8 + 4];
            *(float4*)&b[0] = *(const float4*)&Ws[k][tx * 4];
            *(float4*)&b[4] = *(const float4*)&Ws[k][64 + tx * 4];
            #pragma unroll
            for (int i = 0; i < 8; i++)
                #pragma unroll
                for (int j = 0; j < 8; j++)
                    c[i][j] += a[i] * b[j];
        }
        __syncthreads();
    }

    // bias + relu + store (cols: tx*4..tx*4+3 and 64+tx*4..)
    float bv[8];
    #pragma unroll
    for (int j = 0; j < 4; j++) {
        bv[j]     = g_bias[tx * 4 + j];
        bv[4 + j] = g_bias[64 + tx * 4 + j];
    }
    #pragma unroll
    for (int i = 0; i < 8; i++) {
        int m = m0 + ty * 8 + i;
        if (m < n_nodes) {
            float4 o0, o1;
            o0.x = fmaxf(c[i][0] + bv[0], 0.f);
            o0.y = fmaxf(c[i][1] + bv[1], 0.f);
            o0.z = fmaxf(c[i][2] + bv[2], 0.f);
            o0.w = fmaxf(c[i][3] + bv[3], 0.f);
            o1.x = fmaxf(c[i][4] + bv[4], 0.f);
            o1.y = fmaxf(c[i][5] + bv[5], 0.f);
            o1.z = fmaxf(c[i][6] + bv[6], 0.f);
            o1.w = fmaxf(c[i][7] + bv[7], 0.f);
            *(float4*)(out + (size_t)m * EMB_DIM + tx * 4)      = o0;
            *(float4*)(out + (size_t)m * EMB_DIM + 64 + tx * 4) = o1;
        }
    }
}

// ---------------------------------------------------------------------------
// inputs (metadata order): node_feat, edge_feat, src_idx, W_edge, b_edge, W_lin, b_lin
// ---------------------------------------------------------------------------
extern "C" void kernel_launch(void* const* d_in, const int* in_sizes, int n_in,
                              void* d_out, int out_size) {
    const float* node_feat = (const float*)d_in[0];
    const float* edge_feat = (const float*)d_in[1];
    const int*   src_idx   = (const int*)  d_in[2];
    const float* W_edge    = (const float*)d_in[3];
    const float* b_edge    = (const float*)d_in[4];
    const float* W_lin     = (const float*)d_in[5];
    const float* b_lin     = (const float*)d_in[6];
    float*       out       = (float*)d_out;

    (void)in_sizes; (void)n_in; (void)out_size;

    prep_weights<<<KTOT + 1, EMB_DIM>>>(W_edge, b_edge, W_lin, b_lin);

    int agg_blocks = (NNODES * 32 + 255) / 256;   // warp per node, 8 nodes/block
    aggregate<<<agg_blocks, 256>>>(node_feat, edge_feat, src_idx);

    int gemm_blocks = (NNODES + MT - 1) / MT;
    fused_out_gemm<<<gemm_blocks, 256>>>(node_feat, out, NNODES);
}

// round 3
// speedup vs baseline: 1.3877x; 1.3877x over previous
#include <cuda_runtime.h>
#include <cuda_bf16.h>
#include <cstdint>

#define NNODES   100000
#define SSAMP    16
#define NODE_DIM 128
#define EDGE_DIM 64
#define EMB_DIM  128
#define KTOT     320            // 128 self + 128 neigh-agg + 64 edge-mean

// ---------------- scratch (__device__ globals; no allocation allowed) -------
__device__ float g_A [(size_t)NNODES * NODE_DIM];    // mean of gathered src node feats
__device__ float g_Eb[(size_t)NNODES * EDGE_DIM];    // mean of edge feats per node
__device__ __align__(16) __nv_bfloat16 g_Wh[EMB_DIM * KTOT];  // folded W, transposed [n][k], hi
__device__ __align__(16) __nv_bfloat16 g_Wl[EMB_DIM * KTOT];  // lo
__device__ float g_bias[EMB_DIM];

__device__ __forceinline__ uint32_t smem_u32(const void* p) {
    uint32_t a;
    asm("{ .reg .u64 t; cvta.to.shared.u64 t, %1; cvt.u32.u64 %0, t; }" : "=r"(a) : "l"(p));
    return a;
}
__device__ __forceinline__ void ldsm_x4(uint32_t* r, uint32_t addr) {
    asm volatile("ldmatrix.sync.aligned.m8n8.x4.shared.b16 {%0,%1,%2,%3}, [%4];"
        : "=r"(r[0]), "=r"(r[1]), "=r"(r[2]), "=r"(r[3]) : "r"(addr));
}
__device__ __forceinline__ void mma16816(float* d, const uint32_t* a, const uint32_t* b) {
    asm volatile("mma.sync.aligned.m16n8k16.row.col.f32.bf16.bf16.f32 "
        "{%0,%1,%2,%3}, {%4,%5,%6,%7}, {%8,%9}, {%0,%1,%2,%3};"
        : "+f"(d[0]), "+f"(d[1]), "+f"(d[2]), "+f"(d[3])
        : "r"(a[0]), "r"(a[1]), "r"(a[2]), "r"(a[3]), "r"(b[0]), "r"(b[1]));
}

// ===========================================================================
// K1: aggregation (warp-per-node) + weight fold merged into one launch.
// ===========================================================================
#define AGGB 12500          // = NNODES*32/256
#define FOLDB 41

__global__ __launch_bounds__(256) void aggregate_and_fold(
        const float* __restrict__ node_feat,
        const float* __restrict__ edge_feat,
        const int*   __restrict__ src_idx,
        const float* __restrict__ W_edge,
        const float* __restrict__ b_edge,
        const float* __restrict__ W_lin,
        const float* __restrict__ b_lin) {
    if (blockIdx.x >= AGGB) {
        int kid = blockIdx.x - AGGB;           // 0..40
        if (kid == 40) {
            int j = threadIdx.x;
            if (j < EMB_DIM) {
                float acc = b_lin[j];
                for (int c = 0; c < NODE_DIM; c++)
                    acc += b_edge[c] * W_lin[(NODE_DIM + c) * EMB_DIM + j];
                g_bias[j] = acc;
            }
            return;
        }
        int kk = threadIdx.x >> 7;             // 0/1
        int j  = threadIdx.x & 127;            // output col n
        #pragma unroll
        for (int r = 0; r < 4; r++) {
            int k = kid * 8 + r * 2 + kk;      // 0..319
            float w;
            if (k < 2 * NODE_DIM) {
                w = W_lin[k * EMB_DIM + j];
            } else {
                int e = k - 2 * NODE_DIM;
                float acc = 0.f;
                #pragma unroll 4
                for (int c = 0; c < NODE_DIM; c++)
                    acc += W_edge[e * NODE_DIM + c] * W_lin[(NODE_DIM + c) * EMB_DIM + j];
                w = acc;
            }
            __nv_bfloat16 h = __float2bfloat16_rn(w);
            g_Wh[j * KTOT + k] = h;
            g_Wl[j * KTOT + k] = __float2bfloat16_rn(w - __bfloat162float(h));
        }
        return;
    }

    // ----- aggregation (unchanged from passing round-1 kernel) -----
    int node = (int)((blockIdx.x * blockDim.x + threadIdx.x) >> 5);
    if (node >= NNODES) return;
    int lane = threadIdx.x & 31;

    const float* ep = edge_feat + (size_t)node * (SSAMP * EDGE_DIM);
    int halfrow = lane >> 4;
    int cg      = lane & 15;
    float4 ea = make_float4(0.f, 0.f, 0.f, 0.f);
    #pragma unroll
    for (int r = 0; r < SSAMP; r += 2) {
        float4 v = *(const float4*)(ep + (size_t)(r + halfrow) * EDGE_DIM + cg * 4);
        ea.x += v.x; ea.y += v.y; ea.z += v.z; ea.w += v.w;
    }

    int s = 0;
    if (lane < SSAMP) s = src_idx[(size_t)node * SSAMP + lane];
    float4 na = make_float4(0.f, 0.f, 0.f, 0.f);
    #pragma unroll
    for (int r = 0; r < SSAMP; r++) {
        int sr = __shfl_sync(0xffffffffu, s, r);
        float4 v = *(const float4*)(node_feat + (size_t)sr * NODE_DIM + lane * 4);
        na.x += v.x; na.y += v.y; na.z += v.z; na.w += v.w;
    }

    ea.x += __shfl_xor_sync(0xffffffffu, ea.x, 16);
    ea.y += __shfl_xor_sync(0xffffffffu, ea.y, 16);
    ea.z += __shfl_xor_sync(0xffffffffu, ea.z, 16);
    ea.w += __shfl_xor_sync(0xffffffffu, ea.w, 16);

    const float inv = 1.0f / (float)SSAMP;
    if (lane < 16) {
        float4 o = make_float4(ea.x * inv, ea.y * inv, ea.z * inv, ea.w * inv);
        *(float4*)(g_Eb + (size_t)node * EDGE_DIM + cg * 4) = o;
    }
    float4 on = make_float4(na.x * inv, na.y * inv, na.z * inv, na.w * inv);
    *(float4*)(g_A + (size_t)node * NODE_DIM + lane * 4) = on;
}

// ===========================================================================
// K2: mma.sync split-bf16 GEMM.
//   out = relu( X @ Wall + bias ),  X = [node_feat | g_A | g_Eb]  (K = 320)
//   X@W ~= Xh@Wh + Xl@Wh + Xh@Wl
//   CTA: 128x128, 8 warps (warp tile 32x64), KC=32 chunks (10), 2 ksteps each.
// ===========================================================================
#define AS 80                         // padded smem row stride (40 halfs) - conflict-free ldmatrix

__global__ __launch_bounds__(256) void gemm_mma(const float* __restrict__ node_feat,
                                                float* __restrict__ out) {
    __shared__ __align__(16) unsigned char sAh[128 * AS];
    __shared__ __align__(16) unsigned char sAl[128 * AS];
    __shared__ __align__(16) unsigned char sBh[128 * AS];
    __shared__ __align__(16) unsigned char sBl[128 * AS];
    __shared__ float sBias[EMB_DIM];

    const int tid  = threadIdx.x;
    const int lane = tid & 31;
    const int wid  = tid >> 5;
    const int mw   = (wid & 3) * 32;          // warp M origin within tile
    const int nw   = (wid >> 2) * 64;         // warp N origin within tile
    const int m0   = blockIdx.x * 128;

    if (tid < EMB_DIM) sBias[tid] = g_bias[tid];

    const uint32_t sAh32 = smem_u32(sAh);
    const uint32_t sAl32 = smem_u32(sAl);
    const uint32_t sBh32 = smem_u32(sBh);
    const uint32_t sBl32 = smem_u32(sBl);

    // lane-derived ldmatrix offsets
    const uint32_t aoff = (uint32_t)((mw + (lane & 15)) * AS + (lane >> 4) * 16);
    const uint32_t boff = (uint32_t)((nw + ((lane >> 4) << 3) + (lane & 7)) * AS
                                     + ((lane >> 3) & 1) * 16);

    float C[2][8][4];
    #pragma unroll
    for (int a = 0; a < 2; a++)
        #pragma unroll
        for (int j = 0; j < 8; j++)
            #pragma unroll
            for (int q = 0; q < 4; q++) C[a][j][q] = 0.f;

    #pragma unroll 1
    for (int ch = 0; ch < 10; ch++) {
        if (ch) __syncthreads();

        // ---- stage A chunk: 128 rows x 32 k fp32 -> bf16 hi/lo ----
        const float* src;
        int stride, koff;
        if (ch < 4)      { src = node_feat; stride = NODE_DIM; koff = ch * 32; }
        else if (ch < 8) { src = g_A;       stride = NODE_DIM; koff = (ch - 4) * 32; }
        else             { src = g_Eb;      stride = EDGE_DIM; koff = (ch - 8) * 32; }

        #pragma unroll
        for (int i = 0; i < 4; i++) {
            int idx = tid + i * 256;          // 0..1023
            int r = idx >> 3, q = idx & 7;    // row, float4-group (k)
            int m = m0 + r;
            float4 v = make_float4(0.f, 0.f, 0.f, 0.f);
            if (m < NNODES)
                v = *(const float4*)(src + (size_t)m * stride + koff + q * 4);
            __nv_bfloat16 hx = __float2bfloat16_rn(v.x);
            __nv_bfloat16 hy = __float2bfloat16_rn(v.y);
            __nv_bfloat16 hz = __float2bfloat16_rn(v.z);
            __nv_bfloat16 hw = __float2bfloat16_rn(v.w);
            __nv_bfloat162 h01 = __halves2bfloat162(hx, hy);
            __nv_bfloat162 h23 = __halves2bfloat162(hz, hw);
            __nv_bfloat162 l01 = __floats2bfloat162_rn(v.x - __bfloat162float(hx),
                                                       v.y - __bfloat162float(hy));
            __nv_bfloat162 l23 = __floats2bfloat162_rn(v.z - __bfloat162float(hz),
                                                       v.w - __bfloat162float(hw));
            *(uint2*)(sAh + r * AS + q * 8) = make_uint2(*(uint32_t*)&h01, *(uint32_t*)&h23);
            *(uint2*)(sAl + r * AS + q * 8) = make_uint2(*(uint32_t*)&l01, *(uint32_t*)&l23);
        }

        // ---- stage B chunk: 128 n-rows x 32 k bf16 hi/lo ----
        #pragma unroll
        for (int i = 0; i < 2; i++) {
            int idx = tid + i * 256;          // 0..511
            int n = idx >> 2, u = idx & 3;    // n-row, 16B unit (8 halfs)
            size_t gb = (size_t)n * (KTOT * 2) + (size_t)ch * 64 + (size_t)u * 16;
            *(uint4*)(sBh + n * AS + u * 16) = *(const uint4*)((const char*)g_Wh + gb);
            *(uint4*)(sBl + n * AS + u * 16) = *(const uint4*)((const char*)g_Wl + gb);
        }
        __syncthreads();

        // ---- compute: 2 ksteps x 3 split products ----
        #pragma unroll
        for (int s = 0; s < 2; s++) {
            const uint32_t kb = (uint32_t)(s * 32);   // 16 halfs = 32 bytes
            uint32_t ah[2][4], al[2][4], bb[16];

            ldsm_x4(ah[0], sAh32 + aoff + kb);
            ldsm_x4(ah[1], sAh32 + aoff + 16 * AS + kb);
            #pragma unroll
            for (int p = 0; p < 4; p++)
                ldsm_x4(&bb[4 * p], sBh32 + boff + (uint32_t)(p * 16 * AS) + kb);

            #pragma unroll
            for (int a = 0; a < 2; a++)
                #pragma unroll
                for (int j = 0; j < 8; j++)
                    mma16816(C[a][j], ah[a], &bb[j * 2]);

            ldsm_x4(al[0], sAl32 + aoff + kb);
            ldsm_x4(al[1], sAl32 + aoff + 16 * AS + kb);
            #pragma unroll
            for (int a = 0; a < 2; a++)
                #pragma unroll
                for (int j = 0; j < 8; j++)
                    mma16816(C[a][j], al[a], &bb[j * 2]);

            #pragma unroll
            for (int p = 0; p < 4; p++)
                ldsm_x4(&bb[4 * p], sBl32 + boff + (uint32_t)(p * 16 * AS) + kb);
            #pragma unroll
            for (int a = 0; a < 2; a++)
                #pragma unroll
                for (int j = 0; j < 8; j++)
                    mma16816(C[a][j], ah[a], &bb[j * 2]);
        }
    }

    // ---- epilogue: bias + relu -> out ----
    #pragma unroll
    for (int a = 0; a < 2; a++) {
        int row = m0 + mw + a * 16 + (lane >> 2);
        #pragma unroll
        for (int j = 0; j < 8; j++) {
            int col = nw + j * 8 + 2 * (lane & 3);
            float bx = sBias[col], by = sBias[col + 1];
            if (row < NNODES) {
                float2 o;
                o.x = fmaxf(C[a][j][0] + bx, 0.f);
                o.y = fmaxf(C[a][j][1] + by, 0.f);
                *(float2*)(out + (size_t)row * EMB_DIM + col) = o;
            }
            if (row + 8 < NNODES) {
                float2 o;
                o.x = fmaxf(C[a][j][2] + bx, 0.f);
                o.y = fmaxf(C[a][j][3] + by, 0.f);
                *(float2*)(out + (size_t)(row + 8) * EMB_DIM + col) = o;
            }
        }
    }
}

// ===========================================================================
// inputs: node_feat, edge_feat, src_idx, W_edge, b_edge, W_lin, b_lin
// ===========================================================================
extern "C" void kernel_launch(void* const* d_in, const int* in_sizes, int n_in,
                              void* d_out, int out_size) {
    const float* node_feat = (const float*)d_in[0];
    const float* edge_feat = (const float*)d_in[1];
    const int*   src_idx   = (const int*)  d_in[2];
    const float* W_edge    = (const float*)d_in[3];
    const float* b_edge    = (const float*)d_in[4];
    const float* W_lin     = (const float*)d_in[5];
    const float* b_lin     = (const float*)d_in[6];
    float*       out       = (float*)d_out;
    (void)in_sizes; (void)n_in; (void)out_size;

    aggregate_and_fold<<<AGGB + FOLDB, 256>>>(node_feat, edge_feat, src_idx,
                                              W_edge, b_edge, W_lin, b_lin);

    int gemm_blocks = (NNODES + 127) / 128;   // 782
    gemm_mma<<<gemm_blocks, 256>>>(node_feat, out);
}